// round 16
// baseline (speedup 1.0000x reference)
#include <cuda_runtime.h>

// Problem constants
#define BB    8
#define TT    2048
#define CIN   7
#define CC    8
#define NCH   128      // chunks per batch
#define NSEG  48       // segments per batch: 32 x 3 chunks + 16 x 2 chunks
#define NBLK  384      // persistent blocks = BB * NSEG
#define NT    256      // threads per block
#define SIZE  4680
#define STRIDE 4736
#define O2    8
#define O3    72
#define O4    584
#define HDIM  256
#define NSL   32       // gemv slices
#define SLW   147

#define NTASK3 (BB * NCH)      // 1024 apply tasks
#define NTASK4 (BB * NSL)      // 256 pool/gemv tasks

// Scratch (device globals -- no runtime allocation)
__device__ __align__(16) float g_bufB[(size_t)BB * NCH * STRIDE];   // local prefixes
__device__ __align__(16) float g_bufA[(size_t)BB * NCH * STRIDE];   // logs
__device__ __align__(16) float g_T[(size_t)BB * 64 * STRIDE];       // scanned totals P[e]
__device__ __align__(16) float g_hp[NSL * BB * HDIM];
// Sync state: each counter on its OWN 128B line.
__device__ __align__(128) unsigned int g_bar[32];
__device__ __align__(128) unsigned int g_t3[32];
__device__ __align__(128) unsigned int g_t4[32];

// segment s: chunks [segc0(s), segc0(s)+segnc(s))
__device__ __forceinline__ int segc0(int s) { return (s < 32) ? 3 * s : 2 * s + 32; }
__device__ __forceinline__ int segnc(int s) { return (s < 32) ? 3 : 2; }
__device__ __forceinline__ int seglast(int s) { return (s < 32) ? 3 * s + 2 : 2 * s + 33; }

// ---------------------------------------------------------------------------
// Device-wide barrier. Co-residency: __launch_bounds__(256,3) -> 444 >= 384.
// ---------------------------------------------------------------------------
__device__ __forceinline__ void gsync(unsigned int idx)
{
    __syncthreads();
    if (threadIdx.x == 0) {
        __threadfence();
        atomicAdd(&g_bar[0], 1u);
        unsigned int target = idx * NBLK;
        volatile unsigned int* p = &g_bar[0];
        while (*p < target) { }
        __threadfence();
    }
    __syncthreads();
}

// ---------------------------------------------------------------------------
// Group merge Od = A (x) B. 256 threads. smem: al, bl (584 each).
// ---------------------------------------------------------------------------
__device__ void ta_merge(const float* __restrict__ A, const float* __restrict__ Bp,
                         float* __restrict__ Od, float* sm, int tid)
{
    float* al = sm;
    float* bl = sm + 584;
    for (int t = tid; t < O4; t += NT) { al[t] = __ldcg(A + t); bl[t] = __ldcg(Bp + t); }
    __syncthreads();

    for (int t = tid; t < O4; t += NT) {
        float r;
        if (t >= O3) {
            int q = t - O3;
            r = al[t] + bl[t] + al[q >> 6] * bl[O2 + (q & 63)]
              + al[O2 + (q >> 3)] * bl[q & 7];
        } else if (t >= O2) {
            int u = t - O2;
            r = al[t] + bl[t] + al[u >> 3] * bl[u & 7];
        } else {
            r = al[t] + bl[t];
        }
        Od[t] = r;
    }
    float a1r[8];
    #pragma unroll
    for (int i = 0; i < 8; i++) a1r[i] = al[i];
    float4 b1v = *(const float4*)&bl[(4 * tid) & 7];
    float4 b2v = *(const float4*)&bl[O2 + ((4 * tid) & 63)];
    float4 b3v = *(const float4*)&bl[O3 + 4 * (tid & 127)];
    #pragma unroll
    for (int m4 = 0; m4 < 4; m4++) {
        int p = 4 * tid + 1024 * m4;
        float a1 = a1r[(tid >> 7) + 2 * m4];
        float a2 = al[O2 + (tid >> 4) + 16 * m4];
        float a3 = al[O3 + (tid >> 1) + 128 * m4];
        float4 Av = __ldcg((const float4*)(A + O4 + p));
        float4 Bv = __ldcg((const float4*)(Bp + O4 + p));
        float4 o;
        o.x = Av.x + Bv.x + a1 * b3v.x + a2 * b2v.x + a3 * b1v.x;
        o.y = Av.y + Bv.y + a1 * b3v.y + a2 * b2v.y + a3 * b1v.y;
        o.z = Av.z + Bv.z + a1 * b3v.z + a2 * b2v.z + a3 * b1v.z;
        o.w = Av.w + Bv.w + a1 * b3v.w + a2 * b2v.w + a3 * b1v.w;
        *(float4*)(Od + O4 + p) = o;
    }
}

// ---------------------------------------------------------------------------
// apply+log: group element = A (x) L (or just L if A == 0); log -> S.
// ---------------------------------------------------------------------------
__device__ void apply_one(const float* __restrict__ L, const float* __restrict__ A,
                          float* __restrict__ S, float* sm, int tid)
{
    float* s    = sm;
    float* al   = sm + 584;
    float* blw  = sm + 1168;
    float* P2_2 = sm + 1752;
    float* P2_3 = sm + 1824;
    float* P3_3 = sm + 2336;

    float4 r4v[4];

    if (A == 0) {
        for (int t = tid; t < O4; t += NT) s[t] = __ldcg(L + t);
        #pragma unroll
        for (int m4 = 0; m4 < 4; m4++)
            r4v[m4] = __ldcg((const float4*)(L + O4 + 4 * tid + 1024 * m4));
    } else {
        for (int t = tid; t < O4; t += NT) { al[t] = __ldcg(A + t); blw[t] = __ldcg(L + t); }
        __syncthreads();
        for (int t = tid; t < O4; t += NT) {
            float r;
            if (t >= O3) {
                int q = t - O3;
                r = al[t] + blw[t]
                  + al[q >> 6]        * blw[O2 + (q & 63)]
                  + al[O2 + (q >> 3)] * blw[q & 7];
            } else if (t >= O2) {
                int u = t - O2;
                r = al[t] + blw[t] + al[u >> 3] * blw[u & 7];
            } else {
                r = al[t] + blw[t];
            }
            s[t] = r;
        }
        float a1r[8];
        #pragma unroll
        for (int i = 0; i < 8; i++) a1r[i] = al[i];
        float4 b1v = *(const float4*)&blw[(4 * tid) & 7];
        float4 b2v = *(const float4*)&blw[O2 + ((4 * tid) & 63)];
        float4 b3v = *(const float4*)&blw[O3 + 4 * (tid & 127)];
        #pragma unroll
        for (int m4 = 0; m4 < 4; m4++) {
            int p = 4 * tid + 1024 * m4;
            float a1 = a1r[(tid >> 7) + 2 * m4];
            float a2 = al[O2 + (tid >> 4) + 16 * m4];
            float a3 = al[O3 + (tid >> 1) + 128 * m4];
            float4 Av = __ldcg((const float4*)(A + O4 + p));
            float4 Lv = __ldcg((const float4*)(L + O4 + p));
            float4 o;
            o.x = Av.x + Lv.x + a1 * b3v.x + a2 * b2v.x + a3 * b1v.x;
            o.y = Av.y + Lv.y + a1 * b3v.y + a2 * b2v.y + a3 * b1v.y;
            o.z = Av.z + Lv.z + a1 * b3v.z + a2 * b2v.z + a3 * b1v.z;
            o.w = Av.w + Lv.w + a1 * b3v.w + a2 * b2v.w + a3 * b1v.w;
            r4v[m4] = o;
        }
    }
    __syncthreads();

    float s1r[8];
    #pragma unroll
    for (int i = 0; i < 8; i++) s1r[i] = s[i];
    float4 s1v = *(const float4*)&s[(4 * tid) & 7];
    float4 s2v = *(const float4*)&s[O2 + ((4 * tid) & 63)];
    float4 s3v = *(const float4*)&s[O3 + 4 * (tid & 127)];
    float s2f = s[O2 + (tid & 63)], s1f = s[tid & 7];
    float s3a = s[O3 + tid], s3b = s[O3 + tid + 256];

    #pragma unroll
    for (int m4 = 0; m4 < 4; m4++) {
        float a1 = s1r[(tid >> 7) + 2 * m4];
        float a2 = s[O2 + (tid >> 4) + 16 * m4];
        float a3 = s[O3 + (tid >> 1) + 128 * m4];
        r4v[m4].x -= 0.5f * (a1 * s3v.x + a2 * s2v.x + a3 * s1v.x);
        r4v[m4].y -= 0.5f * (a1 * s3v.y + a2 * s2v.y + a3 * s1v.y);
        r4v[m4].z -= 0.5f * (a1 * s3v.z + a2 * s2v.z + a3 * s1v.z);
        r4v[m4].w -= 0.5f * (a1 * s3v.w + a2 * s2v.w + a3 * s1v.w);
    }
    {
        float pa = s1r[tid >> 6] * s2f + s[O2 + (tid >> 3)] * s1f;
        float pb = s1r[(tid >> 6) + 4] * s2f + s[O2 + (tid >> 3) + 32] * s1f;
        P2_3[tid] = pa; P2_3[tid + 256] = pb;
    }
    if (tid < 64) P2_2[tid] = s1r[tid >> 3] * s[tid & 7];
    __syncthreads();

    {
        float4 P23v = *(const float4*)&P2_3[4 * (tid & 127)];
        float4 P22v = *(const float4*)&P2_2[(4 * tid) & 63];
        #pragma unroll
        for (int m4 = 0; m4 < 4; m4++) {
            float a1 = s1r[(tid >> 7) + 2 * m4];
            float a2 = s[O2 + (tid >> 4) + 16 * m4];
            r4v[m4].x += (1.0f / 3.0f) * (a1 * P23v.x + a2 * P22v.x);
            r4v[m4].y += (1.0f / 3.0f) * (a1 * P23v.y + a2 * P22v.y);
            r4v[m4].z += (1.0f / 3.0f) * (a1 * P23v.z + a2 * P22v.z);
            r4v[m4].w += (1.0f / 3.0f) * (a1 * P23v.w + a2 * P22v.w);
        }
        float P22a = P2_2[tid & 63];
        P3_3[tid]       = s1r[tid >> 6] * P22a;
        P3_3[tid + 256] = s1r[(tid >> 6) + 4] * P22a;
    }
    __syncthreads();

    {
        float4 P33v = *(const float4*)&P3_3[4 * (tid & 127)];
        #pragma unroll
        for (int m4 = 0; m4 < 4; m4++) {
            float a1 = s1r[(tid >> 7) + 2 * m4];
            r4v[m4].x -= 0.25f * a1 * P33v.x;
            r4v[m4].y -= 0.25f * a1 * P33v.y;
            r4v[m4].z -= 0.25f * a1 * P33v.z;
            r4v[m4].w -= 0.25f * a1 * P33v.w;
            *(float4*)&S[O4 + 4 * tid + 1024 * m4] = r4v[m4];
        }
        S[O3 + tid]       = s3a - 0.5f * P2_3[tid]       + (1.0f / 3.0f) * P3_3[tid];
        S[O3 + tid + 256] = s3b - 0.5f * P2_3[tid + 256] + (1.0f / 3.0f) * P3_3[tid + 256];
    }
    if (tid < 64) S[O2 + tid] = s[O2 + tid] - 0.5f * P2_2[tid];
    if (tid < 8)  S[tid] = s1r[tid];
}

// ---------------------------------------------------------------------------
// THE single fused kernel. 384 blocks x 256 threads (3/SM).
// ---------------------------------------------------------------------------
__global__ void __launch_bounds__(NT, 3)
k_fused(const float* __restrict__ x,
        const float* __restrict__ W1,
        const float* __restrict__ b1,
        const float* __restrict__ W2,
        const float* __restrict__ b2,
        float* __restrict__ out)
{
    __shared__ __align__(16) float sm[2848];
    __shared__ int s_task;
    int blk = blockIdx.x;
    int tid = threadIdx.x;

    // warm L2 with W1 for phase 4
    {
        size_t nbytes = (size_t)SIZE * HDIM * 4;
        size_t loff = ((size_t)blk * NT + tid) * 128;
        if (loff < nbytes)
            asm volatile("prefetch.global.L2 [%0];" :: "l"((const char*)W1 + loff));
    }

    // ============ Phase 1: 2-step-fused Chen, ONE segment per block =========
    // Segment sizes 3 or 2 chunks (48/32 steps); makespan = 24 fused iters.
    {
        const int l = tid & 7, k = (tid >> 3) & 7, j0 = tid >> 6;
        float* d   = sm;          // up to 384 = [48][8]
        float* cb0 = sm + 384;
        float* cb1 = sm + 968;

        int b = blk / NSEG, seg = blk - b * NSEG;
        int c0 = segc0(seg), nc = segnc(seg);
        int nsteps = nc * 16;
        int t0 = c0 * 16;

        for (int idx = tid; idx < nsteps * CC; idx += NT) {
            int s = idx >> 3, ch = idx & 7;
            int t = t0 + s;
            float v;
            if (ch < CIN) {
                float cur  = __ldg(&x[(b * TT + t) * CIN + ch]);
                float prev = (t > 0) ? __ldg(&x[(b * TT + t - 1) * CIN + ch]) : 0.0f;
                v = cur - prev;
            } else {
                v = (t > 0) ? (1.0f / 2047.0f) : 0.0f;
            }
            d[idx] = v;
        }
        __syncthreads();

        float r4[16], c1r[8];
        // ---- iter 0: carry := F(d0, d1) ----
        {
            float al = d[l], bl = d[8 + l], ak = d[k], bk = d[8 + k];
            float bkbl = bk * bl;
            float w1 = ak * ((1.0f / 6.0f) * al + 0.5f * bl) + 0.5f * bkbl;
            float w2 = (1.0f / 6.0f) * bkbl;
            float aje = d[j0], bje = d[8 + j0], ajo = d[j0 + 4], bjo = d[8 + j0 + 4];
            float F3_e = aje * w1 + bje * w2;
            float F3_o = ajo * w1 + bjo * w2;
            float u4 = ak * ((1.0f / 24.0f) * al + (1.0f / 6.0f) * bl) + 0.25f * bkbl;
            float v4 = (1.0f / 6.0f) * bkbl;
            float ge = aje * u4 + bje * v4, he = (1.0f / 24.0f) * bje * bkbl;
            float go = ajo * u4 + bjo * v4, ho = (1.0f / 24.0f) * bjo * bkbl;
            #pragma unroll
            for (int m = 0; m < 16; m++)
                r4[m] = d[m >> 1] * ((m & 1) ? go : ge)
                      + d[8 + (m >> 1)] * ((m & 1) ? ho : he);
            #pragma unroll
            for (int i = 0; i < 8; i++) c1r[i] = d[i] + d[8 + i];
            cb0[64 + tid] = F3_e;
            cb0[64 + tid + 256] = F3_o;
            if (tid < 64) {
                int xx = tid >> 3, yy = tid & 7;
                cb0[tid] = 0.5f * d[xx] * d[yy] + d[xx] * d[8 + yy]
                         + 0.5f * d[8 + xx] * d[8 + yy];
            }
            __syncthreads();
        }
        // ---- iters 1..(8*nc - 1) ----
        int niter = 8 * nc;
        for (int it = 1; it < niter; it++) {
            float* cc = (it & 1) ? cb0 : cb1;
            float* cn = (it & 1) ? cb1 : cb0;
            const float* da = d + 16 * it;
            const float* db = da + 8;
            float al = da[l], bl = db[l], ak = da[k], bk = db[k];
            float el = al + bl;
            float bkbl = bk * bl;
            float F2_kl = 0.5f * ak * al + ak * bl + 0.5f * bkbl;
            float w1 = ak * ((1.0f / 6.0f) * al + 0.5f * bl) + 0.5f * bkbl;
            float w2 = (1.0f / 6.0f) * bkbl;
            float aje = da[j0], bje = db[j0], ajo = da[j0 + 4], bjo = db[j0 + 4];
            float F3_e = aje * w1 + bje * w2;
            float F3_o = ajo * w1 + bjo * w2;
            float u4 = ak * ((1.0f / 24.0f) * al + (1.0f / 6.0f) * bl) + 0.25f * bkbl;
            float v4 = (1.0f / 6.0f) * bkbl;
            float ge = aje * u4 + bje * v4, he = (1.0f / 24.0f) * bje * bkbl;
            float go = ajo * u4 + bjo * v4, ho = (1.0f / 24.0f) * bjo * bkbl;
            #pragma unroll
            for (int m = 0; m < 16; m++) {
                float c3v = cc[64 + (tid >> 3) + 32 * m];
                float c2v = cc[(tid >> 6) + 4 * m];
                float F3j = (m & 1) ? F3_o : F3_e;
                float F4m = da[m >> 1] * ((m & 1) ? go : ge)
                          + db[m >> 1] * ((m & 1) ? ho : he);
                r4[m] += F4m + c1r[m >> 1] * F3j + c2v * F2_kl + c3v * el;
            }
            float t3a = cc[64 + tid] + F3_e + cc[tid >> 3] * el + c1r[j0] * F2_kl;
            float t3b = cc[64 + tid + 256] + F3_o + cc[(tid >> 3) + 32] * el
                      + c1r[j0 + 4] * F2_kl;
            float t2v = 0.0f;
            if (tid < 64) {
                int xx = tid >> 3, yy = tid & 7;
                t2v = cc[tid] + 0.5f * da[xx] * da[yy] + da[xx] * db[yy]
                    + 0.5f * db[xx] * db[yy] + c1r[xx] * (da[yy] + db[yy]);
            }
            #pragma unroll
            for (int i = 0; i < 8; i++) c1r[i] += da[i] + db[i];
            cn[64 + tid] = t3a;
            cn[64 + tid + 256] = t3b;
            if (tid < 64) cn[tid] = t2v;
            __syncthreads();
            if ((it & 7) == 7) {   // chunk snapshot
                float* o = g_bufB + (size_t)(b * NCH + c0 + (it >> 3)) * STRIDE;
                o[O3 + tid] = t3a;
                o[O3 + tid + 256] = t3b;
                if (tid < 64) o[O2 + tid] = t2v;
                if (tid < 8)  o[tid] = c1r[tid];
                #pragma unroll
                for (int m = 0; m < 16; m++) o[O4 + tid + 256 * m] = r4[m];
            }
        }
    }
    gsync(1);

    // ============ Phase 2: Sklansky over 48 totals (padded-64 schedule) =====
    for (int r = 0; r < 6; r++) {
        if (blk < 256) {
            int b = blk >> 5, g = blk & 31;
            int span = 1 << r;
            int base = (g >> r) << (r + 1);
            int e_src = base + span - 1;
            int e_dst = base + span + (g & (span - 1));
            if (e_dst < NSEG) {
                bool bnew = (g & (span - 1)) == 0;
                const float* A = (r == 0)
                    ? g_bufB + (size_t)(b * NCH + seglast(e_src)) * STRIDE
                    : g_T + (size_t)(b * 64 + e_src) * STRIDE;
                const float* Bp = bnew
                    ? g_bufB + (size_t)(b * NCH + seglast(e_dst)) * STRIDE
                    : g_T + (size_t)(b * 64 + e_dst) * STRIDE;
                float* Od = g_T + (size_t)(b * 64 + e_dst) * STRIDE;
                __syncthreads();
                ta_merge(A, Bp, Od, sm, tid);
            }
        }
        gsync(2 + r);
    }

    // ============ Phase 3: apply + log, 1024 stolen tasks ===================
    // Segment-last chunk: prefix == P[s] -> log-only.
    // Other chunks: prefix == P[s-1] (x) local (A==0 for s==0).
    for (;;) {
        __syncthreads();
        if (tid == 0) s_task = (int)atomicAdd(&g_t3[0], 1u);
        __syncthreads();
        int task = s_task;
        if (task >= NTASK3) break;
        int b = task >> 7, n = task & 127;
        int seg, pos, lastpos;
        if (n < 96) { seg = n / 3; pos = n - 3 * seg; lastpos = 2; }
        else        { seg = 32 + ((n - 96) >> 1); pos = (n - 96) & 1; lastpos = 1; }
        const float* L;
        const float* A;
        if (pos == lastpos) {
            L = (seg == 0)
                ? g_bufB + (size_t)(b * NCH + 2) * STRIDE
                : g_T + (size_t)(b * 64 + seg) * STRIDE;
            A = 0;
        } else {
            L = g_bufB + (size_t)(b * NCH + n) * STRIDE;
            A = (seg == 0) ? 0
              : (seg == 1) ? g_bufB + (size_t)(b * NCH + 2) * STRIDE
                           : g_T + (size_t)(b * 64 + seg - 1) * STRIDE;
        }
        float* S = g_bufA + (size_t)(b * NCH + n) * STRIDE;
        apply_one(L, A, S, sm, tid);
    }
    gsync(8);

    // ============ Phase 4: pool + GEMV partials, 256 stolen tasks ===========
    for (;;) {
        __syncthreads();
        if (tid == 0) s_task = (int)atomicAdd(&g_t4[0], 1u);
        __syncthreads();
        int task = s_task;
        if (task >= NTASK4) break;
        int b = task >> 5, sl = task & 31;
        int i0 = sl * SLW;
        int len = SIZE - i0; if (len > SLW) len = SLW;
        float* pv = sm;
        if (tid < len) {
            const float* p = g_bufA + (size_t)b * NCH * STRIDE + i0 + tid;
            float acc = 0.0f;
            #pragma unroll 8
            for (int n = 0; n < NCH; n++) acc += __ldcg(p + (size_t)n * STRIDE);
            pv[tid] = acc * (1.0f / NCH);
        }
        __syncthreads();
        float acc = 0.0f;
        for (int ii = 0; ii < len; ii++)
            acc = fmaf(pv[ii], __ldg(&W1[(size_t)(i0 + ii) * HDIM + tid]), acc);
        g_hp[(sl * BB + b) * HDIM + tid] = acc;
    }
    gsync(9);

    // ============ Final: MLP head (block 0) =================================
    if (blk == 0) {
        float* red = sm;
        __syncthreads();
        for (int bb = 0; bb < BB; bb++) {
            float h = 0.0f;
            #pragma unroll
            for (int sl2 = 0; sl2 < NSL; sl2++)
                h += __ldcg(&g_hp[(sl2 * BB + bb) * HDIM + tid]);
            float v = fmaxf(h + b1[tid], 0.0f) * W2[tid];
            red[tid] = v; __syncthreads();
            for (int s2 = 128; s2 > 0; s2 >>= 1) {
                if (tid < s2) red[tid] += red[tid + s2];
                __syncthreads();
            }
            if (tid == 0) out[bb] = red[0] + b2[0];
            __syncthreads();
        }
        if (tid == 0) { g_bar[0] = 0u; g_t3[0] = 0u; g_t4[0] = 0u; }
    }
}

// ---------------------------------------------------------------------------
extern "C" void kernel_launch(void* const* d_in, const int* in_sizes, int n_in,
                              void* d_out, int out_size)
{
    const float* x  = (const float*)d_in[0];
    const float* W1 = (const float*)d_in[1];
    const float* b1 = (const float*)d_in[2];
    const float* W2 = (const float*)d_in[3];
    const float* b2 = (const float*)d_in[4];
    float* out = (float*)d_out;

    (void)in_sizes; (void)n_in; (void)out_size;

    k_fused<<<NBLK, NT>>>(x, W1, b1, W2, b2, out);
}

// round 17
// speedup vs baseline: 1.0306x; 1.0306x over previous
#include <cuda_runtime.h>

// Problem constants
#define BB    8
#define TT    2048
#define CIN   7
#define CC    8
#define NCH   128      // chunks per batch
#define SEGC  2        // chunks per segment
#define SEGST 32       // time steps per segment
#define NSEG2 64       // segments per batch
#define NBLK  384      // persistent blocks
#define NT    256      // threads per block
#define SIZE  4680
#define STRIDE 4736
#define O2    8
#define O3    72
#define O4    584
#define HDIM  256
#define NSL   32       // gemv slices
#define SLW   147

#define NTASK1 (BB * NSEG2)    // 512 chen tasks
#define NTASK3 (BB * NCH)      // 1024 apply tasks
#define NTASK4 (BB * NSL)      // 256 pool/gemv tasks

// Scratch (device globals -- no runtime allocation)
__device__ __align__(16) float g_bufB[(size_t)BB * NCH * STRIDE];   // local prefixes
__device__ __align__(16) float g_bufA[(size_t)BB * NCH * STRIDE];   // logs
__device__ __align__(16) float g_T[(size_t)BB * NSEG2 * STRIDE];    // scanned totals P[e]
__device__ __align__(16) float g_hp[NSL * BB * HDIM];
// Sync state: each counter on its OWN 128B line.
__device__ __align__(128) unsigned int g_bar[32];
__device__ __align__(128) unsigned int g_t1[32];
__device__ __align__(128) unsigned int g_t3[32];
__device__ __align__(128) unsigned int g_t4[32];

// ---------------------------------------------------------------------------
// Device-wide barrier. Co-residency: __launch_bounds__(256,3) -> 444 >= 384.
// ---------------------------------------------------------------------------
__device__ __forceinline__ void gsync(unsigned int idx)
{
    __syncthreads();
    if (threadIdx.x == 0) {
        __threadfence();
        atomicAdd(&g_bar[0], 1u);
        unsigned int target = idx * NBLK;
        volatile unsigned int* p = &g_bar[0];
        while (*p < target) { }
        __threadfence();
    }
    __syncthreads();
}

// ---------------------------------------------------------------------------
// Group merge Od = A (x) B. 256 threads. smem: al, bl (584 each).
// ---------------------------------------------------------------------------
__device__ void ta_merge(const float* __restrict__ A, const float* __restrict__ Bp,
                         float* __restrict__ Od, float* sm, int tid)
{
    float* al = sm;
    float* bl = sm + 584;
    for (int t = tid; t < O4; t += NT) { al[t] = __ldcg(A + t); bl[t] = __ldcg(Bp + t); }
    __syncthreads();

    for (int t = tid; t < O4; t += NT) {
        float r;
        if (t >= O3) {
            int q = t - O3;
            r = al[t] + bl[t] + al[q >> 6] * bl[O2 + (q & 63)]
              + al[O2 + (q >> 3)] * bl[q & 7];
        } else if (t >= O2) {
            int u = t - O2;
            r = al[t] + bl[t] + al[u >> 3] * bl[u & 7];
        } else {
            r = al[t] + bl[t];
        }
        Od[t] = r;
    }
    float a1r[8];
    #pragma unroll
    for (int i = 0; i < 8; i++) a1r[i] = al[i];
    float4 b1v = *(const float4*)&bl[(4 * tid) & 7];
    float4 b2v = *(const float4*)&bl[O2 + ((4 * tid) & 63)];
    float4 b3v = *(const float4*)&bl[O3 + 4 * (tid & 127)];
    #pragma unroll
    for (int m4 = 0; m4 < 4; m4++) {
        int p = 4 * tid + 1024 * m4;
        float a1 = a1r[(tid >> 7) + 2 * m4];
        float a2 = al[O2 + (tid >> 4) + 16 * m4];
        float a3 = al[O3 + (tid >> 1) + 128 * m4];
        float4 Av = __ldcg((const float4*)(A + O4 + p));
        float4 Bv = __ldcg((const float4*)(Bp + O4 + p));
        float4 o;
        o.x = Av.x + Bv.x + a1 * b3v.x + a2 * b2v.x + a3 * b1v.x;
        o.y = Av.y + Bv.y + a1 * b3v.y + a2 * b2v.y + a3 * b1v.y;
        o.z = Av.z + Bv.z + a1 * b3v.z + a2 * b2v.z + a3 * b1v.z;
        o.w = Av.w + Bv.w + a1 * b3v.w + a2 * b2v.w + a3 * b1v.w;
        *(float4*)(Od + O4 + p) = o;
    }
}

// ---------------------------------------------------------------------------
// apply+log: group element = A (x) L (or just L if A == 0); log -> S.
// ---------------------------------------------------------------------------
__device__ void apply_one(const float* __restrict__ L, const float* __restrict__ A,
                          float* __restrict__ S, float* sm, int tid)
{
    float* s    = sm;
    float* al   = sm + 584;
    float* blw  = sm + 1168;
    float* P2_2 = sm + 1752;
    float* P2_3 = sm + 1824;
    float* P3_3 = sm + 2336;

    float4 r4v[4];

    if (A == 0) {
        for (int t = tid; t < O4; t += NT) s[t] = __ldcg(L + t);
        #pragma unroll
        for (int m4 = 0; m4 < 4; m4++)
            r4v[m4] = __ldcg((const float4*)(L + O4 + 4 * tid + 1024 * m4));
    } else {
        for (int t = tid; t < O4; t += NT) { al[t] = __ldcg(A + t); blw[t] = __ldcg(L + t); }
        __syncthreads();
        for (int t = tid; t < O4; t += NT) {
            float r;
            if (t >= O3) {
                int q = t - O3;
                r = al[t] + blw[t]
                  + al[q >> 6]        * blw[O2 + (q & 63)]
                  + al[O2 + (q >> 3)] * blw[q & 7];
            } else if (t >= O2) {
                int u = t - O2;
                r = al[t] + blw[t] + al[u >> 3] * blw[u & 7];
            } else {
                r = al[t] + blw[t];
            }
            s[t] = r;
        }
        float a1r[8];
        #pragma unroll
        for (int i = 0; i < 8; i++) a1r[i] = al[i];
        float4 b1v = *(const float4*)&blw[(4 * tid) & 7];
        float4 b2v = *(const float4*)&blw[O2 + ((4 * tid) & 63)];
        float4 b3v = *(const float4*)&blw[O3 + 4 * (tid & 127)];
        #pragma unroll
        for (int m4 = 0; m4 < 4; m4++) {
            int p = 4 * tid + 1024 * m4;
            float a1 = a1r[(tid >> 7) + 2 * m4];
            float a2 = al[O2 + (tid >> 4) + 16 * m4];
            float a3 = al[O3 + (tid >> 1) + 128 * m4];
            float4 Av = __ldcg((const float4*)(A + O4 + p));
            float4 Lv = __ldcg((const float4*)(L + O4 + p));
            float4 o;
            o.x = Av.x + Lv.x + a1 * b3v.x + a2 * b2v.x + a3 * b1v.x;
            o.y = Av.y + Lv.y + a1 * b3v.y + a2 * b2v.y + a3 * b1v.y;
            o.z = Av.z + Lv.z + a1 * b3v.z + a2 * b2v.z + a3 * b1v.z;
            o.w = Av.w + Lv.w + a1 * b3v.w + a2 * b2v.w + a3 * b1v.w;
            r4v[m4] = o;
        }
    }
    __syncthreads();

    float s1r[8];
    #pragma unroll
    for (int i = 0; i < 8; i++) s1r[i] = s[i];
    float4 s1v = *(const float4*)&s[(4 * tid) & 7];
    float4 s2v = *(const float4*)&s[O2 + ((4 * tid) & 63)];
    float4 s3v = *(const float4*)&s[O3 + 4 * (tid & 127)];
    float s2f = s[O2 + (tid & 63)], s1f = s[tid & 7];
    float s3a = s[O3 + tid], s3b = s[O3 + tid + 256];

    #pragma unroll
    for (int m4 = 0; m4 < 4; m4++) {
        float a1 = s1r[(tid >> 7) + 2 * m4];
        float a2 = s[O2 + (tid >> 4) + 16 * m4];
        float a3 = s[O3 + (tid >> 1) + 128 * m4];
        r4v[m4].x -= 0.5f * (a1 * s3v.x + a2 * s2v.x + a3 * s1v.x);
        r4v[m4].y -= 0.5f * (a1 * s3v.y + a2 * s2v.y + a3 * s1v.y);
        r4v[m4].z -= 0.5f * (a1 * s3v.z + a2 * s2v.z + a3 * s1v.z);
        r4v[m4].w -= 0.5f * (a1 * s3v.w + a2 * s2v.w + a3 * s1v.w);
    }
    {
        float pa = s1r[tid >> 6] * s2f + s[O2 + (tid >> 3)] * s1f;
        float pb = s1r[(tid >> 6) + 4] * s2f + s[O2 + (tid >> 3) + 32] * s1f;
        P2_3[tid] = pa; P2_3[tid + 256] = pb;
    }
    if (tid < 64) P2_2[tid] = s1r[tid >> 3] * s[tid & 7];
    __syncthreads();

    {
        float4 P23v = *(const float4*)&P2_3[4 * (tid & 127)];
        float4 P22v = *(const float4*)&P2_2[(4 * tid) & 63];
        #pragma unroll
        for (int m4 = 0; m4 < 4; m4++) {
            float a1 = s1r[(tid >> 7) + 2 * m4];
            float a2 = s[O2 + (tid >> 4) + 16 * m4];
            r4v[m4].x += (1.0f / 3.0f) * (a1 * P23v.x + a2 * P22v.x);
            r4v[m4].y += (1.0f / 3.0f) * (a1 * P23v.y + a2 * P22v.y);
            r4v[m4].z += (1.0f / 3.0f) * (a1 * P23v.z + a2 * P22v.z);
            r4v[m4].w += (1.0f / 3.0f) * (a1 * P23v.w + a2 * P22v.w);
        }
        float P22a = P2_2[tid & 63];
        P3_3[tid]       = s1r[tid >> 6] * P22a;
        P3_3[tid + 256] = s1r[(tid >> 6) + 4] * P22a;
    }
    __syncthreads();

    {
        float4 P33v = *(const float4*)&P3_3[4 * (tid & 127)];
        #pragma unroll
        for (int m4 = 0; m4 < 4; m4++) {
            float a1 = s1r[(tid >> 7) + 2 * m4];
            r4v[m4].x -= 0.25f * a1 * P33v.x;
            r4v[m4].y -= 0.25f * a1 * P33v.y;
            r4v[m4].z -= 0.25f * a1 * P33v.z;
            r4v[m4].w -= 0.25f * a1 * P33v.w;
            *(float4*)&S[O4 + 4 * tid + 1024 * m4] = r4v[m4];
        }
        S[O3 + tid]       = s3a - 0.5f * P2_3[tid]       + (1.0f / 3.0f) * P3_3[tid];
        S[O3 + tid + 256] = s3b - 0.5f * P2_3[tid + 256] + (1.0f / 3.0f) * P3_3[tid + 256];
    }
    if (tid < 64) S[O2 + tid] = s[O2 + tid] - 0.5f * P2_2[tid];
    if (tid < 8)  S[tid] = s1r[tid];
}

// ---------------------------------------------------------------------------
// THE single fused kernel. 384 blocks x 256 threads (3/SM), work-stealing.
// ---------------------------------------------------------------------------
__global__ void __launch_bounds__(NT, 3)
k_fused(const float* __restrict__ x,
        const float* __restrict__ W1,
        const float* __restrict__ b1,
        const float* __restrict__ W2,
        const float* __restrict__ b2,
        float* __restrict__ out)
{
    __shared__ __align__(16) float sm[2848];
    __shared__ int s_task;
    int blk = blockIdx.x;
    int tid = threadIdx.x;

    // warm L2 with W1 for phase 4
    {
        size_t nbytes = (size_t)SIZE * HDIM * 4;
        size_t loff = ((size_t)blk * NT + tid) * 128;
        if (loff < nbytes)
            asm volatile("prefetch.global.L2 [%0];" :: "l"((const char*)W1 + loff));
    }

    // ============ Phase 1: 2-step-fused Chen, 512 stolen tasks =============
    // L4 mapping: p = 4*tid + 1024*m4 + e (float4 per m4).
    //   l = l0 + e (l0 = (4tid)&7 in {0,4}); k = (tid>>1)&7 const;
    //   j = (tid>>4)&7 const; i = (tid>>7) + 2*m4.
    //   carry: c3 at (tid>>1)+128*m4, c2 at (tid>>4)+16*m4, c1 at i.
    // Lows keep the original tid-based mapping (own scalars).
    {
        const int l0 = (4 * tid) & 7;
        const int k2 = (tid >> 1) & 7;
        const int j2 = (tid >> 4) & 7;
        const int i0 = tid >> 7;
        const int lo_l = tid & 7, lo_k = (tid >> 3) & 7, lo_j0 = tid >> 6;
        float* d   = sm;          // 512 = [32][8], rows 16B-aligned pairs
        float* cb0 = sm + 512;
        float* cb1 = sm + 1096;
        for (;;) {
            __syncthreads();
            if (tid == 0) s_task = (int)atomicAdd(&g_t1[0], 1u);
            __syncthreads();
            int task = s_task;
            if (task >= NTASK1) break;
            int b = task >> 6, seg = task & 63;

            {   // increments (one per thread: 32 steps x 8 ch = 256)
                int s = tid >> 3, ch = tid & 7;
                int t = seg * SEGST + s;
                float v;
                if (ch < CIN) {
                    float cur  = __ldg(&x[(b * TT + t) * CIN + ch]);
                    float prev = (t > 0) ? __ldg(&x[(b * TT + t - 1) * CIN + ch]) : 0.0f;
                    v = cur - prev;
                } else {
                    v = (t > 0) ? (1.0f / 2047.0f) : 0.0f;
                }
                d[tid] = v;
            }
            __syncthreads();

            float4 r4v[4];
            float c1r[8];
            // ---- iter 0: carry := F(d0, d1) ----
            {
                const float* da = d;
                const float* db = d + 8;
                float4 a_l = *(const float4*)&da[l0];
                float4 b_l = *(const float4*)&db[l0];
                float ak = da[k2], bk = db[k2], aj = da[j2], bj = db[j2];
                float4 bk4, u4v, w2v, gv, hv;
                bk4.x = bk * b_l.x; bk4.y = bk * b_l.y; bk4.z = bk * b_l.z; bk4.w = bk * b_l.w;
                w2v.x = (1.0f/6.0f)*bk4.x; w2v.y = (1.0f/6.0f)*bk4.y;
                w2v.z = (1.0f/6.0f)*bk4.z; w2v.w = (1.0f/6.0f)*bk4.w;
                u4v.x = ak*((1.0f/24.0f)*a_l.x + (1.0f/6.0f)*b_l.x) + 0.25f*bk4.x;
                u4v.y = ak*((1.0f/24.0f)*a_l.y + (1.0f/6.0f)*b_l.y) + 0.25f*bk4.y;
                u4v.z = ak*((1.0f/24.0f)*a_l.z + (1.0f/6.0f)*b_l.z) + 0.25f*bk4.z;
                u4v.w = ak*((1.0f/24.0f)*a_l.w + (1.0f/6.0f)*b_l.w) + 0.25f*bk4.w;
                gv.x = aj*u4v.x + bj*w2v.x; gv.y = aj*u4v.y + bj*w2v.y;
                gv.z = aj*u4v.z + bj*w2v.z; gv.w = aj*u4v.w + bj*w2v.w;
                hv.x = (1.0f/24.0f)*bj*bk4.x; hv.y = (1.0f/24.0f)*bj*bk4.y;
                hv.z = (1.0f/24.0f)*bj*bk4.z; hv.w = (1.0f/24.0f)*bj*bk4.w;
                #pragma unroll
                for (int m4 = 0; m4 < 4; m4++) {
                    int im = i0 + 2 * m4;
                    float ai = da[im], bi = db[im];
                    r4v[m4].x = ai*gv.x + bi*hv.x;
                    r4v[m4].y = ai*gv.y + bi*hv.y;
                    r4v[m4].z = ai*gv.z + bi*hv.z;
                    r4v[m4].w = ai*gv.w + bi*hv.w;
                }
                #pragma unroll
                for (int i = 0; i < 8; i++) c1r[i] = da[i] + db[i];
                // lows (original mapping)
                float al_s = da[lo_l], bl_s = db[lo_l], ak_s = da[lo_k], bk_s = db[lo_k];
                float bkbl_s = bk_s * bl_s;
                float w1s = ak_s*((1.0f/6.0f)*al_s + 0.5f*bl_s) + 0.5f*bkbl_s;
                float w2s = (1.0f/6.0f)*bkbl_s;
                float aje = da[lo_j0], bje = db[lo_j0], ajo = da[lo_j0+4], bjo = db[lo_j0+4];
                cb0[64 + tid]       = aje*w1s + bje*w2s;
                cb0[64 + tid + 256] = ajo*w1s + bjo*w2s;
                if (tid < 64) {
                    int xx = tid >> 3, yy = tid & 7;
                    cb0[tid] = 0.5f*da[xx]*da[yy] + da[xx]*db[yy] + 0.5f*db[xx]*db[yy];
                }
                __syncthreads();
            }
            // ---- iters 1..15 ----
            for (int it = 1; it < 16; it++) {
                float* cc = (it & 1) ? cb0 : cb1;
                float* cn = (it & 1) ? cb1 : cb0;
                const float* da = d + 16 * it;
                const float* db = da + 8;
                float4 a_l = *(const float4*)&da[l0];
                float4 b_l = *(const float4*)&db[l0];
                float ak = da[k2], bk = db[k2], aj = da[j2], bj = db[j2];
                float4 el4, bk4, F2v, w1v, w2v, F3v, u4v, gv, hv;
                el4.x = a_l.x + b_l.x; el4.y = a_l.y + b_l.y;
                el4.z = a_l.z + b_l.z; el4.w = a_l.w + b_l.w;
                bk4.x = bk * b_l.x; bk4.y = bk * b_l.y; bk4.z = bk * b_l.z; bk4.w = bk * b_l.w;
                F2v.x = 0.5f*ak*a_l.x + ak*b_l.x + 0.5f*bk4.x;
                F2v.y = 0.5f*ak*a_l.y + ak*b_l.y + 0.5f*bk4.y;
                F2v.z = 0.5f*ak*a_l.z + ak*b_l.z + 0.5f*bk4.z;
                F2v.w = 0.5f*ak*a_l.w + ak*b_l.w + 0.5f*bk4.w;
                w1v.x = ak*((1.0f/6.0f)*a_l.x + 0.5f*b_l.x) + 0.5f*bk4.x;
                w1v.y = ak*((1.0f/6.0f)*a_l.y + 0.5f*b_l.y) + 0.5f*bk4.y;
                w1v.z = ak*((1.0f/6.0f)*a_l.z + 0.5f*b_l.z) + 0.5f*bk4.z;
                w1v.w = ak*((1.0f/6.0f)*a_l.w + 0.5f*b_l.w) + 0.5f*bk4.w;
                w2v.x = (1.0f/6.0f)*bk4.x; w2v.y = (1.0f/6.0f)*bk4.y;
                w2v.z = (1.0f/6.0f)*bk4.z; w2v.w = (1.0f/6.0f)*bk4.w;
                F3v.x = aj*w1v.x + bj*w2v.x; F3v.y = aj*w1v.y + bj*w2v.y;
                F3v.z = aj*w1v.z + bj*w2v.z; F3v.w = aj*w1v.w + bj*w2v.w;
                u4v.x = ak*((1.0f/24.0f)*a_l.x + (1.0f/6.0f)*b_l.x) + 0.25f*bk4.x;
                u4v.y = ak*((1.0f/24.0f)*a_l.y + (1.0f/6.0f)*b_l.y) + 0.25f*bk4.y;
                u4v.z = ak*((1.0f/24.0f)*a_l.z + (1.0f/6.0f)*b_l.z) + 0.25f*bk4.z;
                u4v.w = ak*((1.0f/24.0f)*a_l.w + (1.0f/6.0f)*b_l.w) + 0.25f*bk4.w;
                gv.x = aj*u4v.x + bj*w2v.x; gv.y = aj*u4v.y + bj*w2v.y;
                gv.z = aj*u4v.z + bj*w2v.z; gv.w = aj*u4v.w + bj*w2v.w;
                hv.x = (1.0f/24.0f)*bj*bk4.x; hv.y = (1.0f/24.0f)*bj*bk4.y;
                hv.z = (1.0f/24.0f)*bj*bk4.z; hv.w = (1.0f/24.0f)*bj*bk4.w;
                #pragma unroll
                for (int m4 = 0; m4 < 4; m4++) {
                    int im = i0 + 2 * m4;
                    float ai = da[im], bi = db[im];
                    float c1v = c1r[im];
                    float c3v = cc[64 + (tid >> 1) + 128 * m4];
                    float c2v = cc[(tid >> 4) + 16 * m4];
                    r4v[m4].x += ai*gv.x + bi*hv.x + c1v*F3v.x + c2v*F2v.x + c3v*el4.x;
                    r4v[m4].y += ai*gv.y + bi*hv.y + c1v*F3v.y + c2v*F2v.y + c3v*el4.y;
                    r4v[m4].z += ai*gv.z + bi*hv.z + c1v*F3v.z + c2v*F2v.z + c3v*el4.z;
                    r4v[m4].w += ai*gv.w + bi*hv.w + c1v*F3v.w + c2v*F2v.w + c3v*el4.w;
                }
                // lows (original mapping, own scalars)
                float al_s = da[lo_l], bl_s = db[lo_l], ak_s = da[lo_k], bk_s = db[lo_k];
                float el_s = al_s + bl_s;
                float bkbl_s = bk_s * bl_s;
                float F2s = 0.5f*ak_s*al_s + ak_s*bl_s + 0.5f*bkbl_s;
                float w1s = ak_s*((1.0f/6.0f)*al_s + 0.5f*bl_s) + 0.5f*bkbl_s;
                float w2s = (1.0f/6.0f)*bkbl_s;
                float aje = da[lo_j0], bje = db[lo_j0], ajo = da[lo_j0+4], bjo = db[lo_j0+4];
                float F3_e = aje*w1s + bje*w2s;
                float F3_o = ajo*w1s + bjo*w2s;
                float t3a = cc[64 + tid] + F3_e + cc[tid >> 3] * el_s + c1r[lo_j0] * F2s;
                float t3b = cc[64 + tid + 256] + F3_o + cc[(tid >> 3) + 32] * el_s
                          + c1r[lo_j0 + 4] * F2s;
                float t2v = 0.0f;
                if (tid < 64) {
                    int xx = tid >> 3, yy = tid & 7;
                    t2v = cc[tid] + 0.5f*da[xx]*da[yy] + da[xx]*db[yy]
                        + 0.5f*db[xx]*db[yy] + c1r[xx]*(da[yy] + db[yy]);
                }
                #pragma unroll
                for (int i = 0; i < 8; i++) c1r[i] += da[i] + db[i];
                cn[64 + tid] = t3a;
                cn[64 + tid + 256] = t3b;
                if (tid < 64) cn[tid] = t2v;
                __syncthreads();
                if ((it & 7) == 7) {   // chunk snapshot
                    float* o = g_bufB + (size_t)(b * NCH + seg * SEGC + (it >> 3)) * STRIDE;
                    o[O3 + tid] = t3a;
                    o[O3 + tid + 256] = t3b;
                    if (tid < 64) o[O2 + tid] = t2v;
                    if (tid < 8)  o[tid] = c1r[tid];
                    #pragma unroll
                    for (int m4 = 0; m4 < 4; m4++)
                        *(float4*)&o[O4 + 4 * tid + 1024 * m4] = r4v[m4];
                }
            }
        }
    }
    gsync(1);

    // ============ Phase 2: Sklansky over 64 segment totals ==================
    for (int r = 0; r < 6; r++) {
        if (blk < 256) {
            int b = blk >> 5, g = blk & 31;
            int span = 1 << r;
            int base = (g >> r) << (r + 1);
            int e_src = base + span - 1;
            int e_dst = base + span + (g & (span - 1));
            bool bnew = (g & (span - 1)) == 0;
            const float* A = (r == 0)
                ? g_bufB + (size_t)(b * NCH + e_src * SEGC + SEGC - 1) * STRIDE
                : g_T + (size_t)(b * NSEG2 + e_src) * STRIDE;
            const float* Bp = bnew
                ? g_bufB + (size_t)(b * NCH + e_dst * SEGC + SEGC - 1) * STRIDE
                : g_T + (size_t)(b * NSEG2 + e_dst) * STRIDE;
            float* Od = g_T + (size_t)(b * NSEG2 + e_dst) * STRIDE;
            __syncthreads();
            ta_merge(A, Bp, Od, sm, tid);
        }
        gsync(2 + r);
    }

    // ============ Phase 3: apply + log, 1024 stolen tasks ===================
    // Odd chunk 2s+1: prefix == P[s] -> log-only.
    // Even chunk 2s : prefix == P[s-1] (x) local(2s) -> merge + log.
    for (;;) {
        __syncthreads();
        if (tid == 0) s_task = (int)atomicAdd(&g_t3[0], 1u);
        __syncthreads();
        int task = s_task;
        if (task >= NTASK3) break;
        int b = task >> 7, n = task & 127;
        int seg = n >> 1;
        const float* L;
        const float* A;
        if (n & 1) {
            L = (seg == 0)
                ? g_bufB + (size_t)(b * NCH + 1) * STRIDE
                : g_T + (size_t)(b * NSEG2 + seg) * STRIDE;
            A = 0;
        } else {
            L = g_bufB + (size_t)(b * NCH + n) * STRIDE;
            A = (seg == 0) ? 0
              : (seg == 1) ? g_bufB + (size_t)(b * NCH + 1) * STRIDE
                           : g_T + (size_t)(b * NSEG2 + seg - 1) * STRIDE;
        }
        float* S = g_bufA + (size_t)(b * NCH + n) * STRIDE;
        apply_one(L, A, S, sm, tid);
    }
    gsync(8);

    // ============ Phase 4: pool + GEMV partials, 256 stolen tasks ===========
    for (;;) {
        __syncthreads();
        if (tid == 0) s_task = (int)atomicAdd(&g_t4[0], 1u);
        __syncthreads();
        int task = s_task;
        if (task >= NTASK4) break;
        int b = task >> 5, sl = task & 31;
        int i0 = sl * SLW;
        int len = SIZE - i0; if (len > SLW) len = SLW;
        float* pv = sm;
        if (tid < len) {
            const float* p = g_bufA + (size_t)b * NCH * STRIDE + i0 + tid;
            float acc = 0.0f;
            #pragma unroll 8
            for (int n = 0; n < NCH; n++) acc += __ldcg(p + (size_t)n * STRIDE);
            pv[tid] = acc * (1.0f / NCH);
        }
        __syncthreads();
        float acc = 0.0f;
        for (int ii = 0; ii < len; ii++)
            acc = fmaf(pv[ii], __ldg(&W1[(size_t)(i0 + ii) * HDIM + tid]), acc);
        g_hp[(sl * BB + b) * HDIM + tid] = acc;
    }
    gsync(9);

    // ============ Final: MLP head (block 0) =================================
    if (blk == 0) {
        float* red = sm;
        __syncthreads();
        for (int bb = 0; bb < BB; bb++) {
            float h = 0.0f;
            #pragma unroll
            for (int sl2 = 0; sl2 < NSL; sl2++)
                h += __ldcg(&g_hp[(sl2 * BB + bb) * HDIM + tid]);
            float v = fmaxf(h + b1[tid], 0.0f) * W2[tid];
            red[tid] = v; __syncthreads();
            for (int s2 = 128; s2 > 0; s2 >>= 1) {
                if (tid < s2) red[tid] += red[tid + s2];
                __syncthreads();
            }
            if (tid == 0) out[bb] = red[0] + b2[0];
            __syncthreads();
        }
        if (tid == 0) { g_bar[0] = 0u; g_t1[0] = 0u; g_t3[0] = 0u; g_t4[0] = 0u; }
    }
}

// ---------------------------------------------------------------------------
extern "C" void kernel_launch(void* const* d_in, const int* in_sizes, int n_in,
                              void* d_out, int out_size)
{
    const float* x  = (const float*)d_in[0];
    const float* W1 = (const float*)d_in[1];
    const float* b1 = (const float*)d_in[2];
    const float* W2 = (const float*)d_in[3];
    const float* b2 = (const float*)d_in[4];
    float* out = (float*)d_out;

    (void)in_sizes; (void)n_in; (void)out_size;

    k_fused<<<NBLK, NT>>>(x, W1, b1, W2, b2, out);
}